// round 1
// baseline (speedup 1.0000x reference)
#include <cuda_runtime.h>
#include <mma.h>
#include <cstdint>

using namespace nvcuda;

// Problem constants (fixed shapes)
#define DMODEL 1024
#define SEQ    2048
#define NB     4
#define MT     (NB * SEQ)   // 8192 total rows

// ---------------- scratch (device globals; no allocation allowed) -----------
__device__ float g_Q[(size_t)MT * DMODEL];          // 32 MB
__device__ float g_K[(size_t)MT * DMODEL];          // 32 MB
__device__ float g_V[(size_t)MT * DMODEL];          // 32 MB
__device__ float g_S[(size_t)NB * SEQ * SEQ];       // 64 MB scores/attn
__device__ float g_W[(size_t)MT * DMODEL];          // 32 MB attn@V
__device__ float g_P[(size_t)MT * DMODEL];          // 32 MB out proj

// ---------------- tf32 WMMA GEMM ---------------------------------------------
// C[M,N] = A[M,K] * op(B)   per batch (blockIdx.z), all dims multiples of tiles.
// BT=true : B is [N,K] row-major (C = A * B^T)      -- "NT"
// BT=false: B is [K,N] row-major (C = A * B)        -- "NN"
constexpr int BM = 128, BN = 128, BK = 32;
constexpr int KP = 36;    // padded K stride in smem (floats), multiple of 4
constexpr int NP = 132;   // padded N stride in smem (floats), multiple of 4

template <bool BT>
__global__ __launch_bounds__(256) void gemm_tf32(
    const float* __restrict__ A, const float* __restrict__ Bm,
    float* __restrict__ C, int M, int N, int K,
    long long sA, long long sB, long long sC)
{
    A  += (long long)blockIdx.z * sA;
    Bm += (long long)blockIdx.z * sB;
    C  += (long long)blockIdx.z * sC;

    __shared__ float As[BM * KP];
    __shared__ float Bs[BT ? (BN * KP) : (BK * NP)];

    const int t    = threadIdx.x;
    const int warp = t >> 5;
    const int wm   = (warp >> 1) * 32;   // warp M origin within block tile
    const int wn   = (warp & 1) * 64;    // warp N origin within block tile
    const int bm   = blockIdx.y * BM;
    const int bn   = blockIdx.x * BN;

    wmma::fragment<wmma::accumulator, 16, 16, 8, float> cf[2][4];
#pragma unroll
    for (int i = 0; i < 2; i++)
#pragma unroll
        for (int j = 0; j < 4; j++) wmma::fill_fragment(cf[i][j], 0.0f);

    for (int kt = 0; kt < K; kt += BK) {
        // Load A tile: 128 x 32 floats (1024 float4, 4 per thread)
#pragma unroll
        for (int i = 0; i < 4; i++) {
            int idx = t + i * 256;
            int r = idx >> 3, c4 = (idx & 7) << 2;
            float4 v = *(const float4*)&A[(long long)(bm + r) * K + kt + c4];
            *(float4*)&As[r * KP + c4] = v;
        }
        if constexpr (BT) {
            // B tile: [128 n][32 k]
#pragma unroll
            for (int i = 0; i < 4; i++) {
                int idx = t + i * 256;
                int r = idx >> 3, c4 = (idx & 7) << 2;
                float4 v = *(const float4*)&Bm[(long long)(bn + r) * K + kt + c4];
                *(float4*)&Bs[r * KP + c4] = v;
            }
        } else {
            // B tile: [32 k][128 n]
#pragma unroll
            for (int i = 0; i < 4; i++) {
                int idx = t + i * 256;
                int r = idx >> 5, c4 = (idx & 31) << 2;
                float4 v = *(const float4*)&Bm[(long long)(kt + r) * N + bn + c4];
                *(float4*)&Bs[r * NP + c4] = v;
            }
        }
        __syncthreads();

#pragma unroll
        for (int ks = 0; ks < BK; ks += 8) {
            wmma::fragment<wmma::matrix_a, 16, 16, 8, wmma::precision::tf32,
                           wmma::row_major> af[2];
#pragma unroll
            for (int i = 0; i < 2; i++) {
                wmma::load_matrix_sync(af[i], &As[(wm + i * 16) * KP + ks], KP);
#pragma unroll
                for (int e = 0; e < af[i].num_elements; e++)
                    af[i].x[e] = wmma::__float_to_tf32(af[i].x[e]);
            }
            if constexpr (BT) {
                wmma::fragment<wmma::matrix_b, 16, 16, 8, wmma::precision::tf32,
                               wmma::col_major> bf[4];
#pragma unroll
                for (int j = 0; j < 4; j++) {
                    wmma::load_matrix_sync(bf[j], &Bs[(wn + j * 16) * KP + ks], KP);
#pragma unroll
                    for (int e = 0; e < bf[j].num_elements; e++)
                        bf[j].x[e] = wmma::__float_to_tf32(bf[j].x[e]);
                }
#pragma unroll
                for (int i = 0; i < 2; i++)
#pragma unroll
                    for (int j = 0; j < 4; j++)
                        wmma::mma_sync(cf[i][j], af[i], bf[j], cf[i][j]);
            } else {
                wmma::fragment<wmma::matrix_b, 16, 16, 8, wmma::precision::tf32,
                               wmma::row_major> bf[4];
#pragma unroll
                for (int j = 0; j < 4; j++) {
                    wmma::load_matrix_sync(bf[j], &Bs[ks * NP + wn + j * 16], NP);
#pragma unroll
                    for (int e = 0; e < bf[j].num_elements; e++)
                        bf[j].x[e] = wmma::__float_to_tf32(bf[j].x[e]);
                }
#pragma unroll
                for (int i = 0; i < 2; i++)
#pragma unroll
                    for (int j = 0; j < 4; j++)
                        wmma::mma_sync(cf[i][j], af[i], bf[j], cf[i][j]);
            }
        }
        __syncthreads();
    }

#pragma unroll
    for (int i = 0; i < 2; i++)
#pragma unroll
        for (int j = 0; j < 4; j++)
            wmma::store_matrix_sync(
                &C[(long long)(bm + wm + i * 16) * N + bn + wn + j * 16],
                cf[i][j], N, wmma::mem_row_major);
}

// ---------------- masked scaled softmax (in place over g_S rows) -------------
// row length SEQ=2048, 256 threads, 8 elems/thread.
// s' = (mask==1) ? -1e9 : s * (1/sqrt(64)); softmax over row.
__global__ __launch_bounds__(256) void softmax_mask(
    float* __restrict__ S, const int* __restrict__ mask)
{
    const long long row = blockIdx.x;
    float* sr = S + row * (long long)SEQ;
    const int* mr = mask + row * (long long)SEQ;
    const int t = threadIdx.x;

    float v[8];
    float mx = -3.0e38f;
#pragma unroll
    for (int i = 0; i < 8; i++) {
        int c = t + i * 256;
        float s = sr[c] * 0.125f;
        if (mr[c] == 1) s = -1e9f;
        v[i] = s;
        mx = fmaxf(mx, s);
    }

    __shared__ float red[8];
#pragma unroll
    for (int o = 16; o; o >>= 1) mx = fmaxf(mx, __shfl_xor_sync(~0u, mx, o));
    if ((t & 31) == 0) red[t >> 5] = mx;
    __syncthreads();
    mx = red[0];
#pragma unroll
    for (int i = 1; i < 8; i++) mx = fmaxf(mx, red[i]);

    float sum = 0.f;
#pragma unroll
    for (int i = 0; i < 8; i++) {
        v[i] = exp2f((v[i] - mx) * 1.4426950408889634f);
        sum += v[i];
    }
#pragma unroll
    for (int o = 16; o; o >>= 1) sum += __shfl_xor_sync(~0u, sum, o);
    __syncthreads();                 // everyone done reading red[] for max
    if ((t & 31) == 0) red[t >> 5] = sum;
    __syncthreads();
    sum = 0.f;
#pragma unroll
    for (int i = 0; i < 8; i++) sum += red[i];
    float inv = 1.0f / sum;
#pragma unroll
    for (int i = 0; i < 8; i++) sr[t + i * 256] = v[i] * inv;
}

// ---------------- residual add + LayerNorm -----------------------------------
__global__ __launch_bounds__(256) void add_layernorm(
    const float* __restrict__ P, const float* __restrict__ R,
    const float* __restrict__ gamma, const float* __restrict__ beta,
    float* __restrict__ O)
{
    const long long row = blockIdx.x;
    const float* pr = P + row * (long long)DMODEL;
    const float* rr = R + row * (long long)DMODEL;
    float* orow = O + row * (long long)DMODEL;
    const int t = threadIdx.x;

    float x[4];
    float s = 0.f;
#pragma unroll
    for (int i = 0; i < 4; i++) {
        int c = t + i * 256;
        x[i] = pr[c] + rr[c];
        s += x[i];
    }

    __shared__ float red[8];
#pragma unroll
    for (int o = 16; o; o >>= 1) s += __shfl_xor_sync(~0u, s, o);
    if ((t & 31) == 0) red[t >> 5] = s;
    __syncthreads();
    s = 0.f;
#pragma unroll
    for (int i = 0; i < 8; i++) s += red[i];
    const float mu = s * (1.0f / DMODEL);

    float vq = 0.f;
#pragma unroll
    for (int i = 0; i < 4; i++) {
        float d = x[i] - mu;
        vq += d * d;
    }
#pragma unroll
    for (int o = 16; o; o >>= 1) vq += __shfl_xor_sync(~0u, vq, o);
    __syncthreads();                 // red[] reuse
    if ((t & 31) == 0) red[t >> 5] = vq;
    __syncthreads();
    vq = 0.f;
#pragma unroll
    for (int i = 0; i < 8; i++) vq += red[i];
    const float rs = rsqrtf(vq * (1.0f / DMODEL) + 1e-5f);

#pragma unroll
    for (int i = 0; i < 4; i++) {
        int c = t + i * 256;
        orow[c] = (x[i] - mu) * rs * gamma[c] + beta[c];
    }
}

// ---------------- launch ------------------------------------------------------
extern "C" void kernel_launch(void* const* d_in, const int* in_sizes, int n_in,
                              void* d_out, int out_size)
{
    (void)in_sizes; (void)n_in; (void)out_size;
    const float* inQ  = (const float*)d_in[0];
    const float* inK  = (const float*)d_in[1];
    const float* inV  = (const float*)d_in[2];
    const int*   mask = (const int*)  d_in[3];
    const float* WQ   = (const float*)d_in[4];
    const float* WK   = (const float*)d_in[5];
    const float* WV   = (const float*)d_in[6];
    const float* WO   = (const float*)d_in[7];
    const float* gam  = (const float*)d_in[8];
    const float* bet  = (const float*)d_in[9];
    float* out = (float*)d_out;

    float *Q, *K, *V, *S, *W, *P;
    cudaGetSymbolAddress((void**)&Q, g_Q);
    cudaGetSymbolAddress((void**)&K, g_K);
    cudaGetSymbolAddress((void**)&V, g_V);
    cudaGetSymbolAddress((void**)&S, g_S);
    cudaGetSymbolAddress((void**)&W, g_W);
    cudaGetSymbolAddress((void**)&P, g_P);

    const dim3 blk(256);
    const long long sQK = (long long)SEQ * DMODEL;   // per-batch Q/K/V stride
    const long long sSS = (long long)SEQ * SEQ;      // per-batch scores stride

    // Projections: [8192,1024] = X[8192,1024] * W[1024,1024]^T
    gemm_tf32<true><<<dim3(DMODEL / BN, MT / BM, 1), blk>>>(
        inQ, WQ, Q, MT, DMODEL, DMODEL, 0, 0, 0);
    gemm_tf32<true><<<dim3(DMODEL / BN, MT / BM, 1), blk>>>(
        inK, WK, K, MT, DMODEL, DMODEL, 0, 0, 0);
    gemm_tf32<true><<<dim3(DMODEL / BN, MT / BM, 1), blk>>>(
        inV, WV, V, MT, DMODEL, DMODEL, 0, 0, 0);

    // Scores: per batch, [2048,2048] = Q[2048,1024] * K[2048,1024]^T
    gemm_tf32<true><<<dim3(SEQ / BN, SEQ / BM, NB), blk>>>(
        Q, K, S, SEQ, SEQ, DMODEL, sQK, sQK, sSS);

    // mask + scale + softmax (in place)
    softmax_mask<<<NB * SEQ, 256>>>(S, mask);

    // attn @ V: per batch, [2048,1024] = A[2048,2048] * V[2048,1024]
    gemm_tf32<false><<<dim3(DMODEL / BN, SEQ / BM, NB), blk>>>(
        S, V, W, SEQ, DMODEL, SEQ, sSS, sQK, sQK);

    // out proj: [8192,1024] = W[8192,1024] * WO[1024,1024]^T
    gemm_tf32<true><<<dim3(DMODEL / BN, MT / BM, 1), blk>>>(
        W, WO, P, MT, DMODEL, DMODEL, 0, 0, 0);

    // residual + layernorm -> d_out
    add_layernorm<<<MT, 256>>>(P, inQ, gam, bet, out);
}

// round 2
// speedup vs baseline: 1.2254x; 1.2254x over previous
#include <cuda_runtime.h>
#include <mma.h>
#include <cstdint>

using namespace nvcuda;

// Problem constants (fixed shapes)
#define DMODEL 1024
#define SEQ    2048
#define NB     4
#define MT     (NB * SEQ)   // 8192 total rows

// ---------------- scratch (device globals; no allocation allowed) -----------
__device__ float g_Q[(size_t)MT * DMODEL];          // 32 MB
__device__ float g_K[(size_t)MT * DMODEL];          // 32 MB
__device__ float g_V[(size_t)MT * DMODEL];          // 32 MB
__device__ float g_S[(size_t)NB * SEQ * SEQ];       // 64 MB scores/attn
__device__ float g_W[(size_t)MT * DMODEL];          // 32 MB attn@V
__device__ float g_P[(size_t)MT * DMODEL];          // 32 MB out proj

// ---------------- tf32 WMMA GEMM, cp.async 4-stage pipeline ------------------
// C[M,N] = A[M,K] * op(B)   per batch (blockIdx.z), all dims multiples of tiles.
// BT=true : B is [N,K] row-major (C = A * B^T)      -- "NT"
// BT=false: B is [K,N] row-major (C = A * B)        -- "NN"
constexpr int BM = 128, BN = 128, BK = 32;
constexpr int KP = 36;    // padded K stride in smem (floats); 36*4=144 B, 16B-aligned rows
constexpr int NP = 132;   // padded N stride in smem (floats); 132*4=528 B, 16B-aligned rows
constexpr int STAGES = 4;

__device__ __forceinline__ void cp16(uint32_t saddr, const void* gptr) {
    asm volatile("cp.async.cg.shared.global [%0], [%1], 16;\n"
                 :: "r"(saddr), "l"(gptr) : "memory");
}
__device__ __forceinline__ void cp_commit() {
    asm volatile("cp.async.commit_group;\n" ::: "memory");
}
__device__ __forceinline__ void cp_wait2() {
    asm volatile("cp.async.wait_group 2;\n" ::: "memory");
}

template <bool BT>
__global__ __launch_bounds__(256) void gemm_tf32(
    const float* __restrict__ A, const float* __restrict__ Bm,
    float* __restrict__ C, int M, int N, int K,
    long long sA, long long sB, long long sC)
{
    A  += (long long)blockIdx.z * sA;
    Bm += (long long)blockIdx.z * sB;
    C  += (long long)blockIdx.z * sC;

    extern __shared__ float smem[];
    constexpr int ASZ = BM * KP;                       // floats per A stage
    constexpr int BSZ = BT ? (BN * KP) : (BK * NP);    // floats per B stage
    float* As = smem;
    float* Bs = smem + STAGES * ASZ;

    const int t    = threadIdx.x;
    const int warp = t >> 5;
    const int wm   = (warp >> 1) * 32;   // warp M origin within block tile
    const int wn   = (warp & 1) * 64;    // warp N origin within block tile
    const int bm   = blockIdx.y * BM;
    const int bn   = blockIdx.x * BN;

    // per-thread load coordinates (constant across stages)
    // A tile: 128 rows x 32 cols -> 1024 float4, 4 per thread
    // B (BT): same shape. B (NN): 32 rows x 128 cols.
    const uint32_t as_base = (uint32_t)__cvta_generic_to_shared(As);
    const uint32_t bs_base = (uint32_t)__cvta_generic_to_shared(Bs);

    auto load_stage = [&](int st, int kt0) {
        uint32_t ab = as_base + (uint32_t)(st * ASZ) * 4u;
        uint32_t bb = bs_base + (uint32_t)(st * BSZ) * 4u;
#pragma unroll
        for (int i = 0; i < 4; i++) {
            int idx = t + i * 256;
            int r = idx >> 3, c4 = (idx & 7) << 2;
            cp16(ab + (uint32_t)(r * KP + c4) * 4u,
                 &A[(long long)(bm + r) * K + kt0 + c4]);
        }
        if constexpr (BT) {
#pragma unroll
            for (int i = 0; i < 4; i++) {
                int idx = t + i * 256;
                int r = idx >> 3, c4 = (idx & 7) << 2;
                cp16(bb + (uint32_t)(r * KP + c4) * 4u,
                     &Bm[(long long)(bn + r) * K + kt0 + c4]);
            }
        } else {
#pragma unroll
            for (int i = 0; i < 4; i++) {
                int idx = t + i * 256;
                int r = idx >> 5, c4 = (idx & 31) << 2;
                cp16(bb + (uint32_t)(r * NP + c4) * 4u,
                     &Bm[(long long)(kt0 + r) * N + bn + c4]);
            }
        }
    };

    wmma::fragment<wmma::accumulator, 16, 16, 8, float> cf[2][4];
#pragma unroll
    for (int i = 0; i < 2; i++)
#pragma unroll
        for (int j = 0; j < 4; j++) wmma::fill_fragment(cf[i][j], 0.0f);

    const int KT = K / BK;

    // prologue: fill STAGES-1 stages
#pragma unroll
    for (int s = 0; s < STAGES - 1; s++) {
        load_stage(s, s * BK);
        cp_commit();
    }

    for (int kt = 0; kt < KT; kt++) {
        cp_wait2();            // stage kt resident
        __syncthreads();       // also proves all warps finished compute(kt-1)

        int f = kt + STAGES - 1;
        if (f < KT) load_stage(f % STAGES, f * BK);   // overwrites stage computed at kt-1: safe
        cp_commit();

        const float* Asw = As + (kt % STAGES) * ASZ;
        const float* Bsw = Bs + (kt % STAGES) * BSZ;

#pragma unroll
        for (int ks = 0; ks < BK; ks += 8) {
            wmma::fragment<wmma::matrix_a, 16, 16, 8, wmma::precision::tf32,
                           wmma::row_major> af[2];
#pragma unroll
            for (int i = 0; i < 2; i++) {
                wmma::load_matrix_sync(af[i], &Asw[(wm + i * 16) * KP + ks], KP);
#pragma unroll
                for (int e = 0; e < af[i].num_elements; e++)
                    af[i].x[e] = wmma::__float_to_tf32(af[i].x[e]);
            }
            if constexpr (BT) {
                wmma::fragment<wmma::matrix_b, 16, 16, 8, wmma::precision::tf32,
                               wmma::col_major> bf[4];
#pragma unroll
                for (int j = 0; j < 4; j++) {
                    wmma::load_matrix_sync(bf[j], &Bsw[(wn + j * 16) * KP + ks], KP);
#pragma unroll
                    for (int e = 0; e < bf[j].num_elements; e++)
                        bf[j].x[e] = wmma::__float_to_tf32(bf[j].x[e]);
                }
#pragma unroll
                for (int i = 0; i < 2; i++)
#pragma unroll
                    for (int j = 0; j < 4; j++)
                        wmma::mma_sync(cf[i][j], af[i], bf[j], cf[i][j]);
            } else {
                wmma::fragment<wmma::matrix_b, 16, 16, 8, wmma::precision::tf32,
                               wmma::row_major> bf[4];
#pragma unroll
                for (int j = 0; j < 4; j++) {
                    wmma::load_matrix_sync(bf[j], &Bsw[ks * NP + wn + j * 16], NP);
#pragma unroll
                    for (int e = 0; e < bf[j].num_elements; e++)
                        bf[j].x[e] = wmma::__float_to_tf32(bf[j].x[e]);
                }
#pragma unroll
                for (int i = 0; i < 2; i++)
#pragma unroll
                    for (int j = 0; j < 4; j++)
                        wmma::mma_sync(cf[i][j], af[i], bf[j], cf[i][j]);
            }
        }
    }

#pragma unroll
    for (int i = 0; i < 2; i++)
#pragma unroll
        for (int j = 0; j < 4; j++)
            wmma::store_matrix_sync(
                &C[(long long)(bm + wm + i * 16) * N + bn + wn + j * 16],
                cf[i][j], N, wmma::mem_row_major);
}

// ---------------- masked scaled softmax (in place over g_S rows) -------------
__global__ __launch_bounds__(256) void softmax_mask(
    float* __restrict__ S, const int* __restrict__ mask)
{
    const long long row = blockIdx.x;
    float* sr = S + row * (long long)SEQ;
    const int* mr = mask + row * (long long)SEQ;
    const int t = threadIdx.x;

    float v[8];
    float mx = -3.0e38f;
#pragma unroll
    for (int i = 0; i < 8; i++) {
        int c = t + i * 256;
        float s = sr[c] * 0.125f;
        if (mr[c] == 1) s = -1e9f;
        v[i] = s;
        mx = fmaxf(mx, s);
    }

    __shared__ float red[8];
#pragma unroll
    for (int o = 16; o; o >>= 1) mx = fmaxf(mx, __shfl_xor_sync(~0u, mx, o));
    if ((t & 31) == 0) red[t >> 5] = mx;
    __syncthreads();
    mx = red[0];
#pragma unroll
    for (int i = 1; i < 8; i++) mx = fmaxf(mx, red[i]);

    float sum = 0.f;
#pragma unroll
    for (int i = 0; i < 8; i++) {
        v[i] = exp2f((v[i] - mx) * 1.4426950408889634f);
        sum += v[i];
    }
#pragma unroll
    for (int o = 16; o; o >>= 1) sum += __shfl_xor_sync(~0u, sum, o);
    __syncthreads();
    if ((t & 31) == 0) red[t >> 5] = sum;
    __syncthreads();
    sum = 0.f;
#pragma unroll
    for (int i = 0; i < 8; i++) sum += red[i];
    float inv = 1.0f / sum;
#pragma unroll
    for (int i = 0; i < 8; i++) sr[t + i * 256] = v[i] * inv;
}

// ---------------- residual add + LayerNorm -----------------------------------
__global__ __launch_bounds__(256) void add_layernorm(
    const float* __restrict__ P, const float* __restrict__ R,
    const float* __restrict__ gamma, const float* __restrict__ beta,
    float* __restrict__ O)
{
    const long long row = blockIdx.x;
    const float* pr = P + row * (long long)DMODEL;
    const float* rr = R + row * (long long)DMODEL;
    float* orow = O + row * (long long)DMODEL;
    const int t = threadIdx.x;

    float x[4];
    float s = 0.f;
#pragma unroll
    for (int i = 0; i < 4; i++) {
        int c = t + i * 256;
        x[i] = pr[c] + rr[c];
        s += x[i];
    }

    __shared__ float red[8];
#pragma unroll
    for (int o = 16; o; o >>= 1) s += __shfl_xor_sync(~0u, s, o);
    if ((t & 31) == 0) red[t >> 5] = s;
    __syncthreads();
    s = 0.f;
#pragma unroll
    for (int i = 0; i < 8; i++) s += red[i];
    const float mu = s * (1.0f / DMODEL);

    float vq = 0.f;
#pragma unroll
    for (int i = 0; i < 4; i++) {
        float d = x[i] - mu;
        vq += d * d;
    }
#pragma unroll
    for (int o = 16; o; o >>= 1) vq += __shfl_xor_sync(~0u, vq, o);
    __syncthreads();
    if ((t & 31) == 0) red[t >> 5] = vq;
    __syncthreads();
    vq = 0.f;
#pragma unroll
    for (int i = 0; i < 8; i++) vq += red[i];
    const float rs = rsqrtf(vq * (1.0f / DMODEL) + 1e-5f);

#pragma unroll
    for (int i = 0; i < 4; i++) {
        int c = t + i * 256;
        orow[c] = (x[i] - mu) * rs * gamma[c] + beta[c];
    }
}

// ---------------- launch ------------------------------------------------------
extern "C" void kernel_launch(void* const* d_in, const int* in_sizes, int n_in,
                              void* d_out, int out_size)
{
    (void)in_sizes; (void)n_in; (void)out_size;
    const float* inQ  = (const float*)d_in[0];
    const float* inK  = (const float*)d_in[1];
    const float* inV  = (const float*)d_in[2];
    const int*   mask = (const int*)  d_in[3];
    const float* WQ   = (const float*)d_in[4];
    const float* WK   = (const float*)d_in[5];
    const float* WV   = (const float*)d_in[6];
    const float* WO   = (const float*)d_in[7];
    const float* gam  = (const float*)d_in[8];
    const float* bet  = (const float*)d_in[9];
    float* out = (float*)d_out;

    float *Q, *K, *V, *S, *W, *P;
    cudaGetSymbolAddress((void**)&Q, g_Q);
    cudaGetSymbolAddress((void**)&K, g_K);
    cudaGetSymbolAddress((void**)&V, g_V);
    cudaGetSymbolAddress((void**)&S, g_S);
    cudaGetSymbolAddress((void**)&W, g_W);
    cudaGetSymbolAddress((void**)&P, g_P);

    constexpr int SMEM_T = STAGES * (BM * KP + BN * KP) * (int)sizeof(float);
    constexpr int SMEM_N = STAGES * (BM * KP + BK * NP) * (int)sizeof(float);
    cudaFuncSetAttribute(gemm_tf32<true>,
                         cudaFuncAttributeMaxDynamicSharedMemorySize, SMEM_T);
    cudaFuncSetAttribute(gemm_tf32<false>,
                         cudaFuncAttributeMaxDynamicSharedMemorySize, SMEM_N);

    const dim3 blk(256);
    const long long sQK = (long long)SEQ * DMODEL;   // per-batch Q/K/V stride
    const long long sSS = (long long)SEQ * SEQ;      // per-batch scores stride

    // Projections: [8192,1024] = X[8192,1024] * W[1024,1024]^T
    gemm_tf32<true><<<dim3(DMODEL / BN, MT / BM, 1), blk, SMEM_T>>>(
        inQ, WQ, Q, MT, DMODEL, DMODEL, 0, 0, 0);
    gemm_tf32<true><<<dim3(DMODEL / BN, MT / BM, 1), blk, SMEM_T>>>(
        inK, WK, K, MT, DMODEL, DMODEL, 0, 0, 0);
    gemm_tf32<true><<<dim3(DMODEL / BN, MT / BM, 1), blk, SMEM_T>>>(
        inV, WV, V, MT, DMODEL, DMODEL, 0, 0, 0);

    // Scores: per batch, [2048,2048] = Q[2048,1024] * K[2048,1024]^T
    gemm_tf32<true><<<dim3(SEQ / BN, SEQ / BM, NB), blk, SMEM_T>>>(
        Q, K, S, SEQ, SEQ, DMODEL, sQK, sQK, sSS);

    // mask + scale + softmax (in place)
    softmax_mask<<<NB * SEQ, 256>>>(S, mask);

    // attn @ V: per batch, [2048,1024] = A[2048,2048] * V[2048,1024]
    gemm_tf32<false><<<dim3(DMODEL / BN, SEQ / BM, NB), blk, SMEM_N>>>(
        S, V, W, SEQ, DMODEL, SEQ, sSS, sQK, sQK);

    // out proj: [8192,1024] = W[8192,1024] * WO[1024,1024]^T
    gemm_tf32<true><<<dim3(DMODEL / BN, MT / BM, 1), blk, SMEM_T>>>(
        W, WO, P, MT, DMODEL, DMODEL, 0, 0, 0);

    // residual + layernorm -> d_out
    add_layernorm<<<MT, 256>>>(P, inQ, gam, bet, out);
}

// round 3
// speedup vs baseline: 1.4628x; 1.1937x over previous
#include <cuda_runtime.h>
#include <mma.h>
#include <cstdint>

using namespace nvcuda;

// Problem constants (fixed shapes)
#define DMODEL 1024
#define SEQ    2048
#define NB     4
#define MT     (NB * SEQ)   // 8192 total rows

// ---------------- scratch (device globals; no allocation allowed) -----------
__device__ float g_Q[(size_t)MT * DMODEL];          // 32 MB (tf32-rounded)
__device__ float g_K[(size_t)MT * DMODEL];          // 32 MB (tf32-rounded)
__device__ float g_V[(size_t)MT * DMODEL];          // 32 MB (tf32-rounded)
__device__ float g_S[(size_t)NB * SEQ * SEQ];       // 64 MB scores/attn
__device__ float g_W[(size_t)MT * DMODEL];          // 32 MB attn@V (tf32-rounded)
__device__ float g_P[(size_t)MT * DMODEL];          // 32 MB out proj
__device__ float g_RQ[(size_t)MT * DMODEL];         // 32 MB rounded inputQ
__device__ float g_RK[(size_t)MT * DMODEL];         // 32 MB rounded inputK
__device__ float g_RV[(size_t)MT * DMODEL];         // 32 MB rounded inputV
__device__ float g_rW[4][(size_t)DMODEL * DMODEL];  // 16 MB rounded WQ,WK,WV,WO

// ---------------- tf32 rounding (once per element) ---------------------------
__device__ __forceinline__ float to_tf32(float x) {
    float y;
    asm("cvt.rna.tf32.f32 %0, %1;\n" : "=f"(y) : "f"(x));
    return y;
}

__global__ __launch_bounds__(256) void round_tf32(
    const float* __restrict__ x, float* __restrict__ y, int n4)
{
    int i = blockIdx.x * 256 + threadIdx.x;
    if (i < n4) {
        float4 v = ((const float4*)x)[i];
        v.x = to_tf32(v.x); v.y = to_tf32(v.y);
        v.z = to_tf32(v.z); v.w = to_tf32(v.w);
        ((float4*)y)[i] = v;
    }
}

// ---------------- tf32 WMMA GEMM, cp.async 3-stage, 64x64 warp tiles ---------
// C[M,N] = A[M,K] * op(B)   per batch (blockIdx.z). Operands MUST already be
// tf32-rounded (low 13 mantissa bits zero) — no per-fragment conversion here.
// BT=true : B is [N,K] row-major (C = A * B^T).  BT=false: B is [K,N].
// RC=true : round C to tf32 on store (it feeds a later GEMM).
constexpr int BM = 128, BN = 256, BK = 32;
constexpr int KP = 36;    // padded smem K stride (floats)
constexpr int NP = 260;   // padded smem N stride (floats) for NN B tile
constexpr int STAGES = 3;

__device__ __forceinline__ void cp16(uint32_t saddr, const void* gptr) {
    asm volatile("cp.async.cg.shared.global [%0], [%1], 16;\n"
                 :: "r"(saddr), "l"(gptr) : "memory");
}
__device__ __forceinline__ void cp_commit() {
    asm volatile("cp.async.commit_group;\n" ::: "memory");
}
__device__ __forceinline__ void cp_wait1() {
    asm volatile("cp.async.wait_group 1;\n" ::: "memory");
}

template <bool BT, bool RC>
__global__ __launch_bounds__(256, 1) void gemm_tf32(
    const float* __restrict__ A, const float* __restrict__ Bm,
    float* __restrict__ C, int M, int N, int K,
    long long sA, long long sB, long long sC)
{
    A  += (long long)blockIdx.z * sA;
    Bm += (long long)blockIdx.z * sB;
    C  += (long long)blockIdx.z * sC;

    extern __shared__ float smem[];
    constexpr int ASZ = BM * KP;                       // floats per A stage
    constexpr int BSZ = BT ? (BN * KP) : (BK * NP);    // floats per B stage
    float* As = smem;
    float* Bs = smem + STAGES * ASZ;

    const int t    = threadIdx.x;
    const int warp = t >> 5;
    const int wm   = (warp >> 2) * 64;   // 2 warps along M
    const int wn   = (warp & 3) * 64;    // 4 warps along N
    const int bm   = blockIdx.y * BM;
    const int bn   = blockIdx.x * BN;

    const uint32_t as_base = (uint32_t)__cvta_generic_to_shared(As);
    const uint32_t bs_base = (uint32_t)__cvta_generic_to_shared(Bs);

    auto load_stage = [&](int st, int kt0) {
        uint32_t ab = as_base + (uint32_t)(st * ASZ) * 4u;
        uint32_t bb = bs_base + (uint32_t)(st * BSZ) * 4u;
        // A tile: 128 x 32 -> 1024 float4
#pragma unroll
        for (int i = 0; i < 4; i++) {
            int idx = t + i * 256;
            int r = idx >> 3, c4 = (idx & 7) << 2;
            cp16(ab + (uint32_t)(r * KP + c4) * 4u,
                 &A[(long long)(bm + r) * K + kt0 + c4]);
        }
        if constexpr (BT) {
            // B tile: 256 n x 32 k -> 2048 float4
#pragma unroll
            for (int i = 0; i < 8; i++) {
                int idx = t + i * 256;
                int r = idx >> 3, c4 = (idx & 7) << 2;
                cp16(bb + (uint32_t)(r * KP + c4) * 4u,
                     &Bm[(long long)(bn + r) * K + kt0 + c4]);
            }
        } else {
            // B tile: 32 k x 256 n -> 2048 float4
#pragma unroll
            for (int i = 0; i < 8; i++) {
                int idx = t + i * 256;
                int r = idx >> 6, c4 = (idx & 63) << 2;
                cp16(bb + (uint32_t)(r * NP + c4) * 4u,
                     &Bm[(long long)(kt0 + r) * N + bn + c4]);
            }
        }
    };

    wmma::fragment<wmma::accumulator, 16, 16, 8, float> cf[4][4];
#pragma unroll
    for (int i = 0; i < 4; i++)
#pragma unroll
        for (int j = 0; j < 4; j++) wmma::fill_fragment(cf[i][j], 0.0f);

    const int KT = K / BK;

    // prologue: fill STAGES-1 stages
#pragma unroll
    for (int s = 0; s < STAGES - 1; s++) {
        load_stage(s, s * BK);
        cp_commit();
    }

    for (int kt = 0; kt < KT; kt++) {
        cp_wait1();            // stage kt resident
        __syncthreads();       // all warps finished compute(kt-1)

        int f = kt + STAGES - 1;
        if (f < KT) load_stage(f % STAGES, f * BK);
        cp_commit();

        const float* Asw = As + (kt % STAGES) * ASZ;
        const float* Bsw = Bs + (kt % STAGES) * BSZ;

#pragma unroll
        for (int ks = 0; ks < BK; ks += 8) {
            wmma::fragment<wmma::matrix_a, 16, 16, 8, wmma::precision::tf32,
                           wmma::row_major> af[4];
#pragma unroll
            for (int i = 0; i < 4; i++)
                wmma::load_matrix_sync(af[i], &Asw[(wm + i * 16) * KP + ks], KP);

            if constexpr (BT) {
                wmma::fragment<wmma::matrix_b, 16, 16, 8, wmma::precision::tf32,
                               wmma::col_major> bf[4];
#pragma unroll
                for (int j = 0; j < 4; j++)
                    wmma::load_matrix_sync(bf[j], &Bsw[(wn + j * 16) * KP + ks], KP);
#pragma unroll
                for (int i = 0; i < 4; i++)
#pragma unroll
                    for (int j = 0; j < 4; j++)
                        wmma::mma_sync(cf[i][j], af[i], bf[j], cf[i][j]);
            } else {
                wmma::fragment<wmma::matrix_b, 16, 16, 8, wmma::precision::tf32,
                               wmma::row_major> bf[4];
#pragma unroll
                for (int j = 0; j < 4; j++)
                    wmma::load_matrix_sync(bf[j], &Bsw[ks * NP + wn + j * 16], NP);
#pragma unroll
                for (int i = 0; i < 4; i++)
#pragma unroll
                    for (int j = 0; j < 4; j++)
                        wmma::mma_sync(cf[i][j], af[i], bf[j], cf[i][j]);
            }
        }
    }

#pragma unroll
    for (int i = 0; i < 4; i++)
#pragma unroll
        for (int j = 0; j < 4; j++) {
            if constexpr (RC) {
#pragma unroll
                for (int e = 0; e < cf[i][j].num_elements; e++)
                    cf[i][j].x[e] = to_tf32(cf[i][j].x[e]);
            }
            wmma::store_matrix_sync(
                &C[(long long)(bm + wm + i * 16) * N + bn + wn + j * 16],
                cf[i][j], N, wmma::mem_row_major);
        }
}

// ---------------- masked scaled softmax (tf32-rounded output) ----------------
__global__ __launch_bounds__(256) void softmax_mask(
    float* __restrict__ S, const int* __restrict__ mask)
{
    const long long row = blockIdx.x;
    float* sr = S + row * (long long)SEQ;
    const int* mr = mask + row * (long long)SEQ;
    const int t = threadIdx.x;

    float v[8];
    float mx = -3.0e38f;
#pragma unroll
    for (int i = 0; i < 8; i++) {
        int c = t + i * 256;
        float s = sr[c] * 0.125f;
        if (mr[c] == 1) s = -1e9f;
        v[i] = s;
        mx = fmaxf(mx, s);
    }

    __shared__ float red[8];
#pragma unroll
    for (int o = 16; o; o >>= 1) mx = fmaxf(mx, __shfl_xor_sync(~0u, mx, o));
    if ((t & 31) == 0) red[t >> 5] = mx;
    __syncthreads();
    mx = red[0];
#pragma unroll
    for (int i = 1; i < 8; i++) mx = fmaxf(mx, red[i]);

    float sum = 0.f;
#pragma unroll
    for (int i = 0; i < 8; i++) {
        v[i] = exp2f((v[i] - mx) * 1.4426950408889634f);
        sum += v[i];
    }
#pragma unroll
    for (int o = 16; o; o >>= 1) sum += __shfl_xor_sync(~0u, sum, o);
    __syncthreads();
    if ((t & 31) == 0) red[t >> 5] = sum;
    __syncthreads();
    sum = 0.f;
#pragma unroll
    for (int i = 0; i < 8; i++) sum += red[i];
    float inv = 1.0f / sum;
#pragma unroll
    for (int i = 0; i < 8; i++) sr[t + i * 256] = to_tf32(v[i] * inv);
}

// ---------------- residual add + LayerNorm -----------------------------------
__global__ __launch_bounds__(256) void add_layernorm(
    const float* __restrict__ P, const float* __restrict__ R,
    const float* __restrict__ gamma, const float* __restrict__ beta,
    float* __restrict__ O)
{
    const long long row = blockIdx.x;
    const float* pr = P + row * (long long)DMODEL;
    const float* rr = R + row * (long long)DMODEL;
    float* orow = O + row * (long long)DMODEL;
    const int t = threadIdx.x;

    float x[4];
    float s = 0.f;
#pragma unroll
    for (int i = 0; i < 4; i++) {
        int c = t + i * 256;
        x[i] = pr[c] + rr[c];
        s += x[i];
    }

    __shared__ float red[8];
#pragma unroll
    for (int o = 16; o; o >>= 1) s += __shfl_xor_sync(~0u, s, o);
    if ((t & 31) == 0) red[t >> 5] = s;
    __syncthreads();
    s = 0.f;
#pragma unroll
    for (int i = 0; i < 8; i++) s += red[i];
    const float mu = s * (1.0f / DMODEL);

    float vq = 0.f;
#pragma unroll
    for (int i = 0; i < 4; i++) {
        float d = x[i] - mu;
        vq += d * d;
    }
#pragma unroll
    for (int o = 16; o; o >>= 1) vq += __shfl_xor_sync(~0u, vq, o);
    __syncthreads();
    if ((t & 31) == 0) red[t >> 5] = vq;
    __syncthreads();
    vq = 0.f;
#pragma unroll
    for (int i = 0; i < 8; i++) vq += red[i];
    const float rs = rsqrtf(vq * (1.0f / DMODEL) + 1e-5f);

#pragma unroll
    for (int i = 0; i < 4; i++) {
        int c = t + i * 256;
        orow[c] = (x[i] - mu) * rs * gamma[c] + beta[c];
    }
}

// ---------------- launch ------------------------------------------------------
extern "C" void kernel_launch(void* const* d_in, const int* in_sizes, int n_in,
                              void* d_out, int out_size)
{
    (void)in_sizes; (void)n_in; (void)out_size;
    const float* inQ  = (const float*)d_in[0];
    const float* inK  = (const float*)d_in[1];
    const float* inV  = (const float*)d_in[2];
    const int*   mask = (const int*)  d_in[3];
    const float* WQ   = (const float*)d_in[4];
    const float* WK   = (const float*)d_in[5];
    const float* WV   = (const float*)d_in[6];
    const float* WO   = (const float*)d_in[7];
    const float* gam  = (const float*)d_in[8];
    const float* bet  = (const float*)d_in[9];
    float* out = (float*)d_out;

    float *Q, *K, *V, *S, *W, *P, *RQ, *RK, *RV, *rW;
    cudaGetSymbolAddress((void**)&Q,  g_Q);
    cudaGetSymbolAddress((void**)&K,  g_K);
    cudaGetSymbolAddress((void**)&V,  g_V);
    cudaGetSymbolAddress((void**)&S,  g_S);
    cudaGetSymbolAddress((void**)&W,  g_W);
    cudaGetSymbolAddress((void**)&P,  g_P);
    cudaGetSymbolAddress((void**)&RQ, g_RQ);
    cudaGetSymbolAddress((void**)&RK, g_RK);
    cudaGetSymbolAddress((void**)&RV, g_RV);
    cudaGetSymbolAddress((void**)&rW, g_rW);
    float* rWQ = rW;
    float* rWK = rW + (size_t)DMODEL * DMODEL;
    float* rWV = rW + 2 * (size_t)DMODEL * DMODEL;
    float* rWO = rW + 3 * (size_t)DMODEL * DMODEL;

    constexpr int SMEM_T = STAGES * (BM * KP + BN * KP) * (int)sizeof(float);
    constexpr int SMEM_N = STAGES * (BM * KP + BK * NP) * (int)sizeof(float);
    cudaFuncSetAttribute(gemm_tf32<true, true>,
                         cudaFuncAttributeMaxDynamicSharedMemorySize, SMEM_T);
    cudaFuncSetAttribute(gemm_tf32<true, false>,
                         cudaFuncAttributeMaxDynamicSharedMemorySize, SMEM_T);
    cudaFuncSetAttribute(gemm_tf32<false, true>,
                         cudaFuncAttributeMaxDynamicSharedMemorySize, SMEM_N);

    const dim3 blk(256);
    const long long sQK = (long long)SEQ * DMODEL;
    const long long sSS = (long long)SEQ * SEQ;

    // Pre-round inputs and weights to tf32 (once per element)
    const int nBig4 = MT * DMODEL / 4;          // 2,097,152 float4
    const int nW4   = DMODEL * DMODEL / 4;      // 262,144 float4
    round_tf32<<<(nBig4 + 255) / 256, 256>>>(inQ, RQ, nBig4);
    round_tf32<<<(nBig4 + 255) / 256, 256>>>(inK, RK, nBig4);
    round_tf32<<<(nBig4 + 255) / 256, 256>>>(inV, RV, nBig4);
    round_tf32<<<(nW4 + 255) / 256, 256>>>(WQ, rWQ, nW4);
    round_tf32<<<(nW4 + 255) / 256, 256>>>(WK, rWK, nW4);
    round_tf32<<<(nW4 + 255) / 256, 256>>>(WV, rWV, nW4);
    round_tf32<<<(nW4 + 255) / 256, 256>>>(WO, rWO, nW4);

    // Projections: [8192,1024] = X * W^T   (outputs rounded: feed later GEMMs)
    gemm_tf32<true, true><<<dim3(DMODEL / BN, MT / BM, 1), blk, SMEM_T>>>(
        RQ, rWQ, Q, MT, DMODEL, DMODEL, 0, 0, 0);
    gemm_tf32<true, true><<<dim3(DMODEL / BN, MT / BM, 1), blk, SMEM_T>>>(
        RK, rWK, K, MT, DMODEL, DMODEL, 0, 0, 0);
    gemm_tf32<true, true><<<dim3(DMODEL / BN, MT / BM, 1), blk, SMEM_T>>>(
        RV, rWV, V, MT, DMODEL, DMODEL, 0, 0, 0);

    // Scores: per batch [2048,2048] = Q * K^T  (raw fp32 out; softmax rounds)
    gemm_tf32<true, false><<<dim3(SEQ / BN, SEQ / BM, NB), blk, SMEM_T>>>(
        Q, K, S, SEQ, SEQ, DMODEL, sQK, sQK, sSS);

    // mask + scale + softmax (in place, tf32-rounded output)
    softmax_mask<<<NB * SEQ, 256>>>(S, mask);

    // attn @ V: per batch [2048,1024] = A * V  (rounded: feeds out proj)
    gemm_tf32<false, true><<<dim3(DMODEL / BN, SEQ / BM, NB), blk, SMEM_N>>>(
        S, V, W, SEQ, DMODEL, SEQ, sSS, sQK, sQK);

    // out proj: [8192,1024] = W * WO^T  (full fp32 out)
    gemm_tf32<true, false><<<dim3(DMODEL / BN, MT / BM, 1), blk, SMEM_T>>>(
        W, rWO, P, MT, DMODEL, DMODEL, 0, 0, 0);

    // residual + layernorm -> d_out
    add_layernorm<<<MT, 256>>>(P, inQ, gam, bet, out);
}